// round 16
// baseline (speedup 1.0000x reference)
#include <cuda_runtime.h>
#include <math.h>
#include <stdint.h>

#define F_IN  1433
#define F_HID 16
#define NMAX  100000
#define EMAX  3200000
#define SCAN_BLK 1024
#define NB_MAX   128

#define SROW 18                          // even -> LDS.64 8B-aligned
#define GEMM_SMEM (25796 * 4)            // W [1433][18] padded -> 103,184 B
#define GEMM_THREADS 384                 // 12 warps

// Scratch (device globals; allocation is forbidden)
__device__ __align__(16) float g_dis [NMAX];
__device__ int   g_is64;
__device__ int   g_done;
__device__ __align__(16) int g_cnt[NMAX];
__device__ int   g_off[NMAX + 1];
__device__ int   g_cur[NMAX];
__device__ int   g_bsum[NB_MAX];
__device__ int   g_bbase[NB_MAX];
__device__ int   g_src[EMAX];
__device__ __align__(16) float g_h1  [NMAX * 16];   // h1 * dis  (pre-scaled)
__device__ __align__(16) float g_h2  [NMAX * 8];    // h2 * dis  (pre-scaled)

typedef unsigned long long u64;
__device__ __forceinline__ u64 pack2(float lo, float hi) {
    u64 r; asm("mov.b64 %0, {%1,%2};" : "=l"(r) : "f"(lo), "f"(hi)); return r;
}
__device__ __forceinline__ void unpack2(u64 v, float& lo, float& hi) {
    asm("mov.b64 {%0,%1}, %2;" : "=f"(lo), "=f"(hi) : "l"(v));
}
__device__ __forceinline__ void fma2(u64& d, u64 a, u64 b) {
    asm("fma.rn.f32x2 %0, %1, %2, %0;" : "+l"(d) : "l"(a), "l"(b));
}
__device__ __forceinline__ void add2(u64& d, u64 a) {
    asm("add.rn.f32x2 %0, %0, %1;" : "+l"(d) : "l"(a));
}
__device__ __forceinline__ void pref_l2(const float* p) {
    asm volatile("prefetch.global.L2 [%0];" :: "l"(p));
}

__device__ __forceinline__ int edge_at(const int* ei32, int idx, int is64) {
    if (is64) return (int)reinterpret_cast<const long long*>(ei32)[idx];
    return ei32[idx];
}

// ---------------------------------------------------------------------------
// (1) init: zero counts + done flag + dtype probe
// ---------------------------------------------------------------------------
__global__ void k_init(int n, const int* __restrict__ ei32, int nwords) {
    int i = blockIdx.x * blockDim.x + threadIdx.x;
    if (i * 4 + 3 < n) {
        *reinterpret_cast<int4*>(&g_cnt[i * 4]) = make_int4(0, 0, 0, 0);
    } else {
#pragma unroll
        for (int j = 0; j < 4; ++j) if (i * 4 + j < n) g_cnt[i * 4 + j] = 0;
    }
    if (i == 0) {
        g_done = 0;
        int is64 = 1;
        int lim = nwords < 256 ? nwords : 256;
        for (int w = 1; w < lim; w += 2)
            if (ei32[w] != 0) { is64 = 0; break; }
        g_is64 = is64;
    }
}

// ---------------------------------------------------------------------------
// (2) count
// ---------------------------------------------------------------------------
__global__ void k_count(const int* __restrict__ ei, int E) {
    int t = blockIdx.x * blockDim.x + threadIdx.x;
    int e = t * 2;
    if (e >= E) return;
    int is64 = g_is64;
    if (e + 1 < E) {
        int d0, d1;
        if (is64) {
            longlong2 v = *reinterpret_cast<const longlong2*>(
                &reinterpret_cast<const long long*>(ei)[E + e]);
            d0 = (int)v.x; d1 = (int)v.y;
        } else {
            int2 v = *reinterpret_cast<const int2*>(&ei[E + e]);
            d0 = v.x; d1 = v.y;
        }
        atomicAdd(&g_cnt[d0], 1);
        atomicAdd(&g_cnt[d1], 1);
    } else {
        atomicAdd(&g_cnt[edge_at(ei, E + e, is64)], 1);
    }
}

// ---------------------------------------------------------------------------
// (3) dis from counts (before gemm1 so its epilogue can scale)
// ---------------------------------------------------------------------------
__global__ void k_dis(int n) {
    int i = blockIdx.x * blockDim.x + threadIdx.x;
    if (i * 4 + 3 < n) {
        int4 c = *reinterpret_cast<const int4*>(&g_cnt[i * 4]);
        float4 d;
        d.x = rsqrtf((float)c.x + 1.0f);
        d.y = rsqrtf((float)c.y + 1.0f);
        d.z = rsqrtf((float)c.z + 1.0f);
        d.w = rsqrtf((float)c.w + 1.0f);
        *reinterpret_cast<float4*>(&g_dis[i * 4]) = d;
    } else {
#pragma unroll
        for (int j = 0; j < 4; ++j)
            if (i * 4 + j < n) g_dis[i * 4 + j] = rsqrtf((float)g_cnt[i * 4 + j] + 1.0f);
    }
}

// ---------------------------------------------------------------------------
// fold-reduce 16 u64 values over 32 lanes with 17 u64-shuffles.
// ---------------------------------------------------------------------------
__device__ __forceinline__ u64 fold16(u64 v[16], int lane) {
#pragma unroll
    for (int s = 0; s < 4; ++s) {
        const int o = 1 << s;
        const int h = 8 >> s;
        const bool hi = (lane & o) != 0;
#pragma unroll
        for (int j = 0; j < h; ++j) {
            u64 send = hi ? v[j] : v[j + h];
            u64 t = __shfl_xor_sync(0xFFFFFFFFu, send, o);
            u64 keep = hi ? v[j + h] : v[j];
            add2(keep, t);
            v[j] = keep;
        }
    }
    u64 t = __shfl_xor_sync(0xFFFFFFFFu, v[0], 16);
    add2(v[0], t);
    return v[0];
}

// one k-iteration of the gemm mainloop
__device__ __forceinline__ void iterbody(int k, const float* wlo, const float* whi,
                                         float a0, float a1, float a2, float a3,
                                         u64* accA, u64* accB) {
    const float* blo = wlo + k * SROW;
    const float* bhi = whi + k * SROW;
    u64 w0 = *reinterpret_cast<const u64*>(blo);
    u64 w1 = *reinterpret_cast<const u64*>(blo + 2);
    u64 w2 = *reinterpret_cast<const u64*>(blo + 4);
    u64 w3 = *reinterpret_cast<const u64*>(blo + 6);
    u64 w4 = *reinterpret_cast<const u64*>(bhi + 8);
    u64 w5 = *reinterpret_cast<const u64*>(bhi + 10);
    u64 w6 = *reinterpret_cast<const u64*>(bhi + 12);
    u64 w7 = *reinterpret_cast<const u64*>(bhi + 14);
    u64 x0 = pack2(a0, a0), x1 = pack2(a1, a1);
    u64 x2 = pack2(a2, a2), x3 = pack2(a3, a3);
    fma2(accA[0], x0, w0);  fma2(accA[1], x0, w1);
    fma2(accA[2], x0, w2);  fma2(accA[3], x0, w3);
    fma2(accA[4], x0, w4);  fma2(accA[5], x0, w5);
    fma2(accA[6], x0, w6);  fma2(accA[7], x0, w7);
    fma2(accA[8],  x1, w0); fma2(accA[9],  x1, w1);
    fma2(accA[10], x1, w2); fma2(accA[11], x1, w3);
    fma2(accA[12], x1, w4); fma2(accA[13], x1, w5);
    fma2(accA[14], x1, w6); fma2(accA[15], x1, w7);
    fma2(accB[0], x2, w0);  fma2(accB[1], x2, w1);
    fma2(accB[2], x2, w2);  fma2(accB[3], x2, w3);
    fma2(accB[4], x2, w4);  fma2(accB[5], x2, w5);
    fma2(accB[6], x2, w6);  fma2(accB[7], x2, w7);
    fma2(accB[8],  x3, w0); fma2(accB[9],  x3, w1);
    fma2(accB[10], x3, w2); fma2(accB[11], x3, w3);
    fma2(accB[12], x3, w4); fma2(accB[13], x3, w5);
    fma2(accB[14], x3, w6); fma2(accB[15], x3, w7);
}

// load one group (4 iters) of x values into buf[16]; kbase = group*128
__device__ __forceinline__ void loadgrp(int kbase, int lane,
                                        const float* xp0, const float* xp1,
                                        const float* xp2, const float* xp3,
                                        float* buf) {
#pragma unroll
    for (int u = 0; u < 4; ++u) {
        int k = kbase + u * 32 + lane;
        buf[u * 4 + 0] = xp0[k];
        buf[u * 4 + 1] = xp1[k];
        buf[u * 4 + 2] = xp2[k];
        buf[u * 4 + 3] = xp3[k];
    }
}

// prefetch one group's lines into L2
__device__ __forceinline__ void prefgrp(int kbase, int lane,
                                        const float* xp0, const float* xp1,
                                        const float* xp2, const float* xp3) {
    int k = kbase + lane * 4;
    pref_l2(xp0 + k);
    pref_l2(xp1 + k);
    pref_l2(xp2 + k);
    pref_l2(xp3 + k);
}

__device__ __forceinline__ void compgrp(int kbase, int lane,
                                        const float* wlo, const float* whi,
                                        const float* buf, u64* accA, u64* accB) {
#pragma unroll
    for (int u = 0; u < 4; ++u) {
        int k = kbase + u * 32 + lane;
        iterbody(k, wlo, whi,
                 buf[u * 4 + 0], buf[u * 4 + 1], buf[u * 4 + 2], buf[u * 4 + 3],
                 accA, accB);
    }
}

// ---------------------------------------------------------------------------
// (4) GEMM1: h1s = (x @ W1) * dis
// ---------------------------------------------------------------------------
__global__ void __launch_bounds__(GEMM_THREADS, 1)
k_gemm1(const float* __restrict__ x, const float* __restrict__ W1, int n) {
    extern __shared__ float sw[];   // [1433][18], element (k,j) at j ^ ((k&16)>>1)
    const int tid = threadIdx.x;

    const float4* W4 = reinterpret_cast<const float4*>(W1);
    for (int p4 = tid; p4 < F_IN * F_HID / 4; p4 += GEMM_THREADS) {
        float4 v = W4[p4];
        int k = p4 >> 2, j = (p4 & 3) * 4;
        int js = j ^ ((k & 16) >> 1);
        float* d = &sw[k * SROW + js];
        d[0] = v.x; d[1] = v.y; d[2] = v.z; d[3] = v.w;
    }
    __syncthreads();

    const int warp = tid >> 5, lane = tid & 31;
    const int r0 = blockIdx.x * 48 + warp * 4;
    if (r0 >= n) return;
    const int swz = (lane & 16) >> 1;
    const float* wlo = sw + swz;
    const float* whi = sw - swz;

    const float* xp0;
    const float* xp1;
    const float* xp2;
    const float* xp3;
    {
        int a = r0, b = r0 + 1, c = r0 + 2, d = r0 + 3;
        if (b >= n) b = n - 1;
        if (c >= n) c = n - 1;
        if (d >= n) d = n - 1;
        xp0 = x + (size_t)a * F_IN;
        xp1 = x + (size_t)b * F_IN;
        xp2 = x + (size_t)c * F_IN;
        xp3 = x + (size_t)d * F_IN;
    }

    u64 accA[16], accB[16];
#pragma unroll
    for (int j = 0; j < 16; ++j) { accA[j] = 0ull; accB[j] = 0ull; }

    float bufA[16], bufB[16];
    loadgrp(0, lane, xp0, xp1, xp2, xp3, bufA);
    prefgrp(2 * 128, lane, xp0, xp1, xp2, xp3);
    prefgrp(3 * 128, lane, xp0, xp1, xp2, xp3);

#pragma unroll 1
    for (int p = 0; p < 5; ++p) {
        int g = 2 * p;
        loadgrp((g + 1) * 128, lane, xp0, xp1, xp2, xp3, bufB);
        int pg0 = g + 4;  if (pg0 > 10) pg0 = 10;
        prefgrp(pg0 * 128, lane, xp0, xp1, xp2, xp3);
        compgrp(g * 128, lane, wlo, whi, bufA, accA, accB);
        loadgrp((g + 2) * 128, lane, xp0, xp1, xp2, xp3, bufA);
        int pg1 = g + 5;  if (pg1 > 10) pg1 = 10;
        prefgrp(pg1 * 128, lane, xp0, xp1, xp2, xp3);
        compgrp((g + 1) * 128, lane, wlo, whi, bufB, accA, accB);
    }
    int kt = 1408 + lane;
    bool ok = kt < F_IN;
    int kc = ok ? kt : 0;
    float t0 = xp0[kc], t1 = xp1[kc], t2 = xp2[kc], t3 = xp3[kc];
    compgrp(10 * 128, lane, wlo, whi, bufA, accA, accB);
    {
        const float* blo = wlo + kc * SROW;
        const float* bhi = whi + kc * SROW;
        u64 w0 = ok ? *reinterpret_cast<const u64*>(blo)      : 0ull;
        u64 w1 = ok ? *reinterpret_cast<const u64*>(blo + 2)  : 0ull;
        u64 w2 = ok ? *reinterpret_cast<const u64*>(blo + 4)  : 0ull;
        u64 w3 = ok ? *reinterpret_cast<const u64*>(blo + 6)  : 0ull;
        u64 w4 = ok ? *reinterpret_cast<const u64*>(bhi + 8)  : 0ull;
        u64 w5 = ok ? *reinterpret_cast<const u64*>(bhi + 10) : 0ull;
        u64 w6 = ok ? *reinterpret_cast<const u64*>(bhi + 12) : 0ull;
        u64 w7 = ok ? *reinterpret_cast<const u64*>(bhi + 14) : 0ull;
        u64 x0 = pack2(t0, t0), x1 = pack2(t1, t1);
        u64 x2 = pack2(t2, t2), x3 = pack2(t3, t3);
        fma2(accA[0], x0, w0);  fma2(accA[1], x0, w1);
        fma2(accA[2], x0, w2);  fma2(accA[3], x0, w3);
        fma2(accA[4], x0, w4);  fma2(accA[5], x0, w5);
        fma2(accA[6], x0, w6);  fma2(accA[7], x0, w7);
        fma2(accA[8],  x1, w0); fma2(accA[9],  x1, w1);
        fma2(accA[10], x1, w2); fma2(accA[11], x1, w3);
        fma2(accA[12], x1, w4); fma2(accA[13], x1, w5);
        fma2(accA[14], x1, w6); fma2(accA[15], x1, w7);
        fma2(accB[0], x2, w0);  fma2(accB[1], x2, w1);
        fma2(accB[2], x2, w2);  fma2(accB[3], x2, w3);
        fma2(accB[4], x2, w4);  fma2(accB[5], x2, w5);
        fma2(accB[6], x2, w6);  fma2(accB[7], x2, w7);
        fma2(accB[8],  x3, w0); fma2(accB[9],  x3, w1);
        fma2(accB[10], x3, w2); fma2(accB[11], x3, w3);
        fma2(accB[12], x3, w4); fma2(accB[13], x3, w5);
        fma2(accB[14], x3, w6); fma2(accB[15], x3, w7);
    }

    u64 sA = fold16(accA, lane);
    u64 sB = fold16(accB, lane);
    int lb = lane & 15;
    int vidx = ((lb & 1) << 3) | ((lb & 2) << 1) | ((lb & 4) >> 1) | ((lb & 8) >> 3);
    int r = ((lane < 16) ? 0 : 2) + (vidx >> 3);
    int p = vidx & 7;
    u64 s = (lane < 16) ? sA : sB;
    int grow = r0 + r;
    if (grow < n) {
        float dd = g_dis[grow];
        float lo, hi; unpack2(s, lo, hi);
        *reinterpret_cast<float2*>(&g_h1[(size_t)grow * 16 + 2 * p]) =
            make_float2(lo * dd, hi * dd);
    }
}

// ---------------------------------------------------------------------------
// (5) blocksum + last-block scan of block sums (fused)
// ---------------------------------------------------------------------------
__global__ void k_blocksum(int n, int nb) {
    __shared__ int swarp[8];
    __shared__ int slast;
    int t = threadIdx.x;
    int base = blockIdx.x * SCAN_BLK + t * 4;
    int s = 0;
    if (base + 3 < n) {
        int4 c = *reinterpret_cast<const int4*>(&g_cnt[base]);
        s = c.x + c.y + c.z + c.w;
    } else {
#pragma unroll
        for (int j = 0; j < 4; ++j) if (base + j < n) s += g_cnt[base + j];
    }
#pragma unroll
    for (int off = 16; off > 0; off >>= 1) s += __shfl_xor_sync(~0u, s, off);
    if ((t & 31) == 0) swarp[t >> 5] = s;
    __syncthreads();
    if (t == 0) {
        int v = 0;
#pragma unroll
        for (int j = 0; j < 8; ++j) v += swarp[j];
        g_bsum[blockIdx.x] = v;
        __threadfence();
        int ticket = atomicAdd(&g_done, 1);
        slast = (ticket == nb - 1) ? 1 : 0;
    }
    __syncthreads();
    if (!slast) return;

    // last block: exclusive-scan the nb block sums (nb <= 128)
    __shared__ int sw2[4];
    int v = (t < nb) ? *(volatile int*)&g_bsum[t] : 0;
    int lane = t & 31, w = t >> 5;
    int incl = v;
#pragma unroll
    for (int off = 1; off < 32; off <<= 1) {
        int o = __shfl_up_sync(~0u, incl, off);
        if (lane >= off) incl += o;
    }
    if (lane == 31 && w < 4) sw2[w] = incl;
    __syncthreads();
    if (t < 128) {
        int wbase = 0;
#pragma unroll
        for (int j = 0; j < 4; ++j) wbase += (j < w) ? sw2[j] : 0;
        incl += wbase;
        if (t < nb) g_bbase[t] = incl - v;
        if (t == nb - 1) g_off[n] = incl;
    }
}

// ---------------------------------------------------------------------------
// (6) offsets
// ---------------------------------------------------------------------------
__global__ void k_offsets(int n) {
    __shared__ int swarp[8];
    int t = threadIdx.x;
    int base = blockIdx.x * SCAN_BLK + t * 4;
    int c0 = 0, c1 = 0, c2 = 0, c3 = 0;
    if (base + 3 < n) {
        int4 c = *reinterpret_cast<const int4*>(&g_cnt[base]);
        c0 = c.x; c1 = c.y; c2 = c.z; c3 = c.w;
    } else {
        if (base + 0 < n) c0 = g_cnt[base + 0];
        if (base + 1 < n) c1 = g_cnt[base + 1];
        if (base + 2 < n) c2 = g_cnt[base + 2];
        if (base + 3 < n) c3 = g_cnt[base + 3];
    }
    int tsum = c0 + c1 + c2 + c3;
    int lane = t & 31, w = t >> 5;
    int incl = tsum;
#pragma unroll
    for (int off = 1; off < 32; off <<= 1) {
        int o = __shfl_up_sync(~0u, incl, off);
        if (lane >= off) incl += o;
    }
    if (lane == 31) swarp[w] = incl;
    __syncthreads();
    int wbase = 0;
#pragma unroll
    for (int j = 0; j < 8; ++j) wbase += (j < w) ? swarp[j] : 0;
    int ex = g_bbase[blockIdx.x] + wbase + incl - tsum;
    int o0 = ex, o1 = ex + c0, o2 = o1 + c1, o3 = o2 + c2;
    if (base + 3 < n) {
        *reinterpret_cast<int4*>(&g_off[base]) = make_int4(o0, o1, o2, o3);
        *reinterpret_cast<int4*>(&g_cur[base]) = make_int4(o0, o1, o2, o3);
    } else {
        if (base + 0 < n) { g_off[base + 0] = o0; g_cur[base + 0] = o0; }
        if (base + 1 < n) { g_off[base + 1] = o1; g_cur[base + 1] = o1; }
        if (base + 2 < n) { g_off[base + 2] = o2; g_cur[base + 2] = o2; }
        if (base + 3 < n) { g_off[base + 3] = o3; g_cur[base + 3] = o3; }
    }
}

// ---------------------------------------------------------------------------
// (7) fill
// ---------------------------------------------------------------------------
__global__ void k_fill(const int* __restrict__ ei, int E) {
    int t = blockIdx.x * blockDim.x + threadIdx.x;
    int e = t * 2;
    if (e >= E) return;
    int is64 = g_is64;
    if (e + 1 < E) {
        int s0, s1, d0, d1;
        if (is64) {
            const long long* ei64 = reinterpret_cast<const long long*>(ei);
            longlong2 sv = *reinterpret_cast<const longlong2*>(&ei64[e]);
            longlong2 dv = *reinterpret_cast<const longlong2*>(&ei64[E + e]);
            s0 = (int)sv.x; s1 = (int)sv.y; d0 = (int)dv.x; d1 = (int)dv.y;
        } else {
            int2 sv = *reinterpret_cast<const int2*>(&ei[e]);
            int2 dv = *reinterpret_cast<const int2*>(&ei[E + e]);
            s0 = sv.x; s1 = sv.y; d0 = dv.x; d1 = dv.y;
        }
        int p0 = atomicAdd(&g_cur[d0], 1);
        int p1 = atomicAdd(&g_cur[d1], 1);
        g_src[p0] = s0;
        g_src[p1] = s1;
    } else {
        int s = edge_at(ei, e, is64);
        int d = edge_at(ei, E + e, is64);
        g_src[atomicAdd(&g_cur[d], 1)] = s;
    }
}

// ---------------------------------------------------------------------------
// (8) agg1 + layer2 fused (2-way edge unroll for MLP)
// ---------------------------------------------------------------------------
__global__ void k_agg1(const float* __restrict__ b1,
                       const float* __restrict__ W2, int n) {
    __shared__ float sb1[16];
    __shared__ float sW2[16 * 7];
    if (threadIdx.x < 16) sb1[threadIdx.x] = b1[threadIdx.x];
    if (threadIdx.x < 16 * 7) sW2[threadIdx.x] = W2[threadIdx.x];
    __syncthreads();

    int gw = (blockIdx.x * blockDim.x + threadIdx.x) >> 5;
    if (gw >= n) return;
    int lane = threadIdx.x & 31;
    int slot = lane >> 2, q = lane & 3;
    int beg = g_off[gw], end = g_off[gw + 1];
    const float4* H = reinterpret_cast<const float4*>(g_h1);
    float4 acc = make_float4(0.f, 0.f, 0.f, 0.f);
    int idx = beg + slot;
    while (idx + 8 < end) {
        int s0 = g_src[idx];
        int s1 = g_src[idx + 8];
        float4 h0 = H[s0 * 4 + q];
        float4 h1v = H[s1 * 4 + q];
        acc.x += h0.x + h1v.x;
        acc.y += h0.y + h1v.y;
        acc.z += h0.z + h1v.z;
        acc.w += h0.w + h1v.w;
        idx += 16;
    }
    if (idx < end) {
        float4 h = H[g_src[idx] * 4 + q];
        acc.x += h.x; acc.y += h.y; acc.z += h.z; acc.w += h.w;
    }
#pragma unroll
    for (int off = 4; off <= 16; off <<= 1) {
        acc.x += __shfl_xor_sync(0xFFFFFFFFu, acc.x, off);
        acc.y += __shfl_xor_sync(0xFFFFFFFFu, acc.y, off);
        acc.z += __shfl_xor_sync(0xFFFFFFFFu, acc.z, off);
        acc.w += __shfl_xor_sync(0xFFFFFFFFu, acc.w, off);
    }
    float dd = g_dis[gw];
    float4 h = H[gw * 4 + q];
    float v0 = fmaxf((acc.x + h.x) * dd + sb1[q * 4 + 0], 0.0f);
    float v1 = fmaxf((acc.y + h.y) * dd + sb1[q * 4 + 1], 0.0f);
    float v2 = fmaxf((acc.z + h.z) * dd + sb1[q * 4 + 2], 0.0f);
    float v3 = fmaxf((acc.w + h.w) * dd + sb1[q * 4 + 3], 0.0f);

    float o[7];
#pragma unroll
    for (int c = 0; c < 7; ++c) {
        o[c] = v0 * sW2[(q * 4 + 0) * 7 + c];
        o[c] = fmaf(v1, sW2[(q * 4 + 1) * 7 + c], o[c]);
        o[c] = fmaf(v2, sW2[(q * 4 + 2) * 7 + c], o[c]);
        o[c] = fmaf(v3, sW2[(q * 4 + 3) * 7 + c], o[c]);
    }
#pragma unroll
    for (int c = 0; c < 7; ++c) {
        o[c] += __shfl_xor_sync(0xFFFFFFFFu, o[c], 1);
        o[c] += __shfl_xor_sync(0xFFFFFFFFu, o[c], 2);
    }
    if (lane == 0) {
        reinterpret_cast<float4*>(g_h2)[gw * 2 + 0] =
            make_float4(o[0] * dd, o[1] * dd, o[2] * dd, o[3] * dd);
        reinterpret_cast<float4*>(g_h2)[gw * 2 + 1] =
            make_float4(o[4] * dd, o[5] * dd, o[6] * dd, 0.0f);
    }
}

// ---------------------------------------------------------------------------
// (9) agg2 + log_softmax fused (2-way edge unroll)
// ---------------------------------------------------------------------------
__global__ void k_agg2(const float* __restrict__ b2, float* __restrict__ out, int n) {
    __shared__ float sb2[8];
    if (threadIdx.x < 7) sb2[threadIdx.x] = b2[threadIdx.x];
    if (threadIdx.x == 7) sb2[7] = 0.0f;
    __syncthreads();

    int gw = (blockIdx.x * blockDim.x + threadIdx.x) >> 5;
    if (gw >= n) return;
    int lane = threadIdx.x & 31;
    int slot = lane >> 1, h = lane & 1;
    int beg = g_off[gw], end = g_off[gw + 1];
    const float4* H = reinterpret_cast<const float4*>(g_h2);
    float4 acc = make_float4(0.f, 0.f, 0.f, 0.f);
    int idx = beg + slot;
    while (idx + 16 < end) {
        int s0 = g_src[idx];
        int s1 = g_src[idx + 16];
        float4 v0 = H[s0 * 2 + h];
        float4 v1 = H[s1 * 2 + h];
        acc.x += v0.x + v1.x;
        acc.y += v0.y + v1.y;
        acc.z += v0.z + v1.z;
        acc.w += v0.w + v1.w;
        idx += 32;
    }
    if (idx < end) {
        float4 v = H[g_src[idx] * 2 + h];
        acc.x += v.x; acc.y += v.y; acc.z += v.z; acc.w += v.w;
    }
#pragma unroll
    for (int off = 2; off <= 16; off <<= 1) {
        acc.x += __shfl_xor_sync(0xFFFFFFFFu, acc.x, off);
        acc.y += __shfl_xor_sync(0xFFFFFFFFu, acc.y, off);
        acc.z += __shfl_xor_sync(0xFFFFFFFFu, acc.z, off);
        acc.w += __shfl_xor_sync(0xFFFFFFFFu, acc.w, off);
    }
    float dd = g_dis[gw];
    float4 hv = H[gw * 2 + h];
    float4 a;
    a.x = (acc.x + hv.x) * dd + sb2[h * 4 + 0];
    a.y = (acc.y + hv.y) * dd + sb2[h * 4 + 1];
    a.z = (acc.z + hv.z) * dd + sb2[h * 4 + 2];
    a.w = (acc.w + hv.w) * dd + sb2[h * 4 + 3];
    float4 b;
    b.x = __shfl_xor_sync(0xFFFFFFFFu, a.x, 1);
    b.y = __shfl_xor_sync(0xFFFFFFFFu, a.y, 1);
    b.z = __shfl_xor_sync(0xFFFFFFFFu, a.z, 1);
    b.w = __shfl_xor_sync(0xFFFFFFFFu, a.w, 1);
    if (lane == 0) {
        float v[7] = {a.x, a.y, a.z, a.w, b.x, b.y, b.z};
        float m = v[0];
#pragma unroll
        for (int c = 1; c < 7; ++c) m = fmaxf(m, v[c]);
        float sum = 0.0f;
#pragma unroll
        for (int c = 0; c < 7; ++c) sum += expf(v[c] - m);
        float lse = logf(sum) + m;
        float* po = out + (size_t)gw * 7;
#pragma unroll
        for (int c = 0; c < 7; ++c) po[c] = v[c] - lse;
    }
}

// ---------------------------------------------------------------------------
extern "C" void kernel_launch(void* const* d_in, const int* in_sizes, int n_in,
                              void* d_out, int out_size) {
    const float* x  = (const float*)d_in[0];
    const int*   ei = (const int*)d_in[1];
    const float* W1 = (const float*)d_in[2];
    const float* b1 = (const float*)d_in[3];
    const float* W2 = (const float*)d_in[4];
    const float* b2 = (const float*)d_in[5];
    float* out = (float*)d_out;

    const int E = in_sizes[1] / 2;
    const int n = in_sizes[0] / F_IN;
    const int nb = (n + SCAN_BLK - 1) / SCAN_BLK;

    cudaFuncSetAttribute(k_gemm1, cudaFuncAttributeMaxDynamicSharedMemorySize,
                         GEMM_SMEM);

    const int T = 256;
    const int Eh = (E + 1) / 2;
    k_init    <<<(n / 4 + T - 1) / T, T>>>(n, ei, in_sizes[1]);          // #1
    k_count   <<<(Eh + T - 1) / T, T>>>(ei, E);                          // #2
    k_dis     <<<(n / 4 + T - 1) / T, T>>>(n);                           // #3
    k_gemm1   <<<(n + 47) / 48, GEMM_THREADS, GEMM_SMEM>>>(x, W1, n);    // #4 (profiled)
    k_blocksum<<<nb, 256>>>(n, nb);                                      // #5 (fused scan)
    k_offsets <<<nb, 256>>>(n);                                          // #6
    k_fill    <<<(Eh + T - 1) / T, T>>>(ei, E);                          // #7
    k_agg1    <<<(n + 7) / 8, 256>>>(b1, W2, n);                         // #8
    k_agg2    <<<(n + 7) / 8, 256>>>(b2, out, n);                        // #9
}

// round 17
// speedup vs baseline: 1.0271x; 1.0271x over previous
#include <cuda_runtime.h>
#include <math.h>
#include <stdint.h>

#define F_IN  1433
#define F_HID 16
#define NMAX  100000
#define EMAX  3200000
#define SCAN_BLK 1024
#define NB_MAX   128

#define SROW 18                          // even -> LDS.64 8B-aligned
#define GEMM_SMEM (25796 * 4)            // W [1433][18] padded -> 103,184 B
#define GEMM_THREADS 256                 // 8 warps; 2 blocks/SM (reg cap 128)

// Scratch (device globals; allocation is forbidden)
__device__ __align__(16) float g_dis [NMAX];
__device__ int   g_is64;
__device__ int   g_done;
__device__ __align__(16) int g_cnt[NMAX];
__device__ int   g_off[NMAX + 1];
__device__ int   g_cur[NMAX];
__device__ int   g_bsum[NB_MAX];
__device__ int   g_bbase[NB_MAX];
__device__ int   g_src[EMAX];
__device__ __align__(16) float g_h1  [NMAX * 16];   // h1 * dis  (pre-scaled)
__device__ __align__(16) float g_h2  [NMAX * 8];    // h2 * dis  (pre-scaled)

typedef unsigned long long u64;
__device__ __forceinline__ u64 pack2(float lo, float hi) {
    u64 r; asm("mov.b64 %0, {%1,%2};" : "=l"(r) : "f"(lo), "f"(hi)); return r;
}
__device__ __forceinline__ void unpack2(u64 v, float& lo, float& hi) {
    asm("mov.b64 {%0,%1}, %2;" : "=f"(lo), "=f"(hi) : "l"(v));
}
__device__ __forceinline__ void fma2(u64& d, u64 a, u64 b) {
    asm("fma.rn.f32x2 %0, %1, %2, %0;" : "+l"(d) : "l"(a), "l"(b));
}
__device__ __forceinline__ void add2(u64& d, u64 a) {
    asm("add.rn.f32x2 %0, %0, %1;" : "+l"(d) : "l"(a));
}
__device__ __forceinline__ void pref_l2(const float* p) {
    asm volatile("prefetch.global.L2 [%0];" :: "l"(p));
}

__device__ __forceinline__ int edge_at(const int* ei32, int idx, int is64) {
    if (is64) return (int)reinterpret_cast<const long long*>(ei32)[idx];
    return ei32[idx];
}

// ---------------------------------------------------------------------------
// (1) init: zero counts + done flag + dtype probe
// ---------------------------------------------------------------------------
__global__ void k_init(int n, const int* __restrict__ ei32, int nwords) {
    int i = blockIdx.x * blockDim.x + threadIdx.x;
    if (i * 4 + 3 < n) {
        *reinterpret_cast<int4*>(&g_cnt[i * 4]) = make_int4(0, 0, 0, 0);
    } else {
#pragma unroll
        for (int j = 0; j < 4; ++j) if (i * 4 + j < n) g_cnt[i * 4 + j] = 0;
    }
    if (i == 0) {
        g_done = 0;
        int is64 = 1;
        int lim = nwords < 256 ? nwords : 256;
        for (int w = 1; w < lim; w += 2)
            if (ei32[w] != 0) { is64 = 0; break; }
        g_is64 = is64;
    }
}

// ---------------------------------------------------------------------------
// (2) count
// ---------------------------------------------------------------------------
__global__ void k_count(const int* __restrict__ ei, int E) {
    int t = blockIdx.x * blockDim.x + threadIdx.x;
    int e = t * 2;
    if (e >= E) return;
    int is64 = g_is64;
    if (e + 1 < E) {
        int d0, d1;
        if (is64) {
            longlong2 v = *reinterpret_cast<const longlong2*>(
                &reinterpret_cast<const long long*>(ei)[E + e]);
            d0 = (int)v.x; d1 = (int)v.y;
        } else {
            int2 v = *reinterpret_cast<const int2*>(&ei[E + e]);
            d0 = v.x; d1 = v.y;
        }
        atomicAdd(&g_cnt[d0], 1);
        atomicAdd(&g_cnt[d1], 1);
    } else {
        atomicAdd(&g_cnt[edge_at(ei, E + e, is64)], 1);
    }
}

// ---------------------------------------------------------------------------
// (3) dis from counts
// ---------------------------------------------------------------------------
__global__ void k_dis(int n) {
    int i = blockIdx.x * blockDim.x + threadIdx.x;
    if (i * 4 + 3 < n) {
        int4 c = *reinterpret_cast<const int4*>(&g_cnt[i * 4]);
        float4 d;
        d.x = rsqrtf((float)c.x + 1.0f);
        d.y = rsqrtf((float)c.y + 1.0f);
        d.z = rsqrtf((float)c.z + 1.0f);
        d.w = rsqrtf((float)c.w + 1.0f);
        *reinterpret_cast<float4*>(&g_dis[i * 4]) = d;
    } else {
#pragma unroll
        for (int j = 0; j < 4; ++j)
            if (i * 4 + j < n) g_dis[i * 4 + j] = rsqrtf((float)g_cnt[i * 4 + j] + 1.0f);
    }
}

// ---------------------------------------------------------------------------
// fold-reduce 16 u64 values over 32 lanes with 17 u64-shuffles.
// ---------------------------------------------------------------------------
__device__ __forceinline__ u64 fold16(u64 v[16], int lane) {
#pragma unroll
    for (int s = 0; s < 4; ++s) {
        const int o = 1 << s;
        const int h = 8 >> s;
        const bool hi = (lane & o) != 0;
#pragma unroll
        for (int j = 0; j < h; ++j) {
            u64 send = hi ? v[j] : v[j + h];
            u64 t = __shfl_xor_sync(0xFFFFFFFFu, send, o);
            u64 keep = hi ? v[j + h] : v[j];
            add2(keep, t);
            v[j] = keep;
        }
    }
    u64 t = __shfl_xor_sync(0xFFFFFFFFu, v[0], 16);
    add2(v[0], t);
    return v[0];
}

// one k-iteration of the gemm mainloop
__device__ __forceinline__ void iterbody(int k, const float* wlo, const float* whi,
                                         float a0, float a1, float a2, float a3,
                                         u64* accA, u64* accB) {
    const float* blo = wlo + k * SROW;
    const float* bhi = whi + k * SROW;
    u64 w0 = *reinterpret_cast<const u64*>(blo);
    u64 w1 = *reinterpret_cast<const u64*>(blo + 2);
    u64 w2 = *reinterpret_cast<const u64*>(blo + 4);
    u64 w3 = *reinterpret_cast<const u64*>(blo + 6);
    u64 w4 = *reinterpret_cast<const u64*>(bhi + 8);
    u64 w5 = *reinterpret_cast<const u64*>(bhi + 10);
    u64 w6 = *reinterpret_cast<const u64*>(bhi + 12);
    u64 w7 = *reinterpret_cast<const u64*>(bhi + 14);
    u64 x0 = pack2(a0, a0), x1 = pack2(a1, a1);
    u64 x2 = pack2(a2, a2), x3 = pack2(a3, a3);
    fma2(accA[0], x0, w0);  fma2(accA[1], x0, w1);
    fma2(accA[2], x0, w2);  fma2(accA[3], x0, w3);
    fma2(accA[4], x0, w4);  fma2(accA[5], x0, w5);
    fma2(accA[6], x0, w6);  fma2(accA[7], x0, w7);
    fma2(accA[8],  x1, w0); fma2(accA[9],  x1, w1);
    fma2(accA[10], x1, w2); fma2(accA[11], x1, w3);
    fma2(accA[12], x1, w4); fma2(accA[13], x1, w5);
    fma2(accA[14], x1, w6); fma2(accA[15], x1, w7);
    fma2(accB[0], x2, w0);  fma2(accB[1], x2, w1);
    fma2(accB[2], x2, w2);  fma2(accB[3], x2, w3);
    fma2(accB[4], x2, w4);  fma2(accB[5], x2, w5);
    fma2(accB[6], x2, w6);  fma2(accB[7], x2, w7);
    fma2(accB[8],  x3, w0); fma2(accB[9],  x3, w1);
    fma2(accB[10], x3, w2); fma2(accB[11], x3, w3);
    fma2(accB[12], x3, w4); fma2(accB[13], x3, w5);
    fma2(accB[14], x3, w6); fma2(accB[15], x3, w7);
}

// load one group (4 iters) of x values into buf[16]; kbase = group*128
__device__ __forceinline__ void loadgrp(int kbase, int lane,
                                        const float* xp0, const float* xp1,
                                        const float* xp2, const float* xp3,
                                        float* buf) {
#pragma unroll
    for (int u = 0; u < 4; ++u) {
        int k = kbase + u * 32 + lane;
        buf[u * 4 + 0] = xp0[k];
        buf[u * 4 + 1] = xp1[k];
        buf[u * 4 + 2] = xp2[k];
        buf[u * 4 + 3] = xp3[k];
    }
}

// prefetch one group's lines into L2
__device__ __forceinline__ void prefgrp(int kbase, int lane,
                                        const float* xp0, const float* xp1,
                                        const float* xp2, const float* xp3) {
    int k = kbase + lane * 4;
    pref_l2(xp0 + k);
    pref_l2(xp1 + k);
    pref_l2(xp2 + k);
    pref_l2(xp3 + k);
}

__device__ __forceinline__ void compgrp(int kbase, int lane,
                                        const float* wlo, const float* whi,
                                        const float* buf, u64* accA, u64* accB) {
#pragma unroll
    for (int u = 0; u < 4; ++u) {
        int k = kbase + u * 32 + lane;
        iterbody(k, wlo, whi,
                 buf[u * 4 + 0], buf[u * 4 + 1], buf[u * 4 + 2], buf[u * 4 + 3],
                 accA, accB);
    }
}

// ---------------------------------------------------------------------------
// (4) GEMM1: h1s = (x @ W1) * dis ; 256 thr, 2 blocks/SM, 32 rows/block
// ---------------------------------------------------------------------------
__global__ void __launch_bounds__(GEMM_THREADS, 2)
k_gemm1(const float* __restrict__ x, const float* __restrict__ W1, int n) {
    extern __shared__ float sw[];   // [1433][18], element (k,j) at j ^ ((k&16)>>1)
    const int tid = threadIdx.x;

    const float4* W4 = reinterpret_cast<const float4*>(W1);
    for (int p4 = tid; p4 < F_IN * F_HID / 4; p4 += GEMM_THREADS) {
        float4 v = W4[p4];
        int k = p4 >> 2, j = (p4 & 3) * 4;
        int js = j ^ ((k & 16) >> 1);
        float* d = &sw[k * SROW + js];
        d[0] = v.x; d[1] = v.y; d[2] = v.z; d[3] = v.w;
    }
    __syncthreads();

    const int warp = tid >> 5, lane = tid & 31;
    const int r0 = blockIdx.x * 32 + warp * 4;
    if (r0 >= n) return;
    const int swz = (lane & 16) >> 1;
    const float* wlo = sw + swz;
    const float* whi = sw - swz;

    const float* xp0;
    const float* xp1;
    const float* xp2;
    const float* xp3;
    {
        int a = r0, b = r0 + 1, c = r0 + 2, d = r0 + 3;
        if (b >= n) b = n - 1;
        if (c >= n) c = n - 1;
        if (d >= n) d = n - 1;
        xp0 = x + (size_t)a * F_IN;
        xp1 = x + (size_t)b * F_IN;
        xp2 = x + (size_t)c * F_IN;
        xp3 = x + (size_t)d * F_IN;
    }

    u64 accA[16], accB[16];
#pragma unroll
    for (int j = 0; j < 16; ++j) { accA[j] = 0ull; accB[j] = 0ull; }

    float bufA[16], bufB[16];
    loadgrp(0, lane, xp0, xp1, xp2, xp3, bufA);
    prefgrp(2 * 128, lane, xp0, xp1, xp2, xp3);
    prefgrp(3 * 128, lane, xp0, xp1, xp2, xp3);

#pragma unroll 1
    for (int p = 0; p < 5; ++p) {
        int g = 2 * p;
        loadgrp((g + 1) * 128, lane, xp0, xp1, xp2, xp3, bufB);
        int pg0 = g + 4;  if (pg0 > 10) pg0 = 10;
        prefgrp(pg0 * 128, lane, xp0, xp1, xp2, xp3);
        compgrp(g * 128, lane, wlo, whi, bufA, accA, accB);
        loadgrp((g + 2) * 128, lane, xp0, xp1, xp2, xp3, bufA);
        int pg1 = g + 5;  if (pg1 > 10) pg1 = 10;
        prefgrp(pg1 * 128, lane, xp0, xp1, xp2, xp3);
        compgrp((g + 1) * 128, lane, wlo, whi, bufB, accA, accB);
    }
    int kt = 1408 + lane;
    bool ok = kt < F_IN;
    int kc = ok ? kt : 0;
    float t0 = xp0[kc], t1 = xp1[kc], t2 = xp2[kc], t3 = xp3[kc];
    compgrp(10 * 128, lane, wlo, whi, bufA, accA, accB);
    {
        const float* blo = wlo + kc * SROW;
        const float* bhi = whi + kc * SROW;
        u64 w0 = ok ? *reinterpret_cast<const u64*>(blo)      : 0ull;
        u64 w1 = ok ? *reinterpret_cast<const u64*>(blo + 2)  : 0ull;
        u64 w2 = ok ? *reinterpret_cast<const u64*>(blo + 4)  : 0ull;
        u64 w3 = ok ? *reinterpret_cast<const u64*>(blo + 6)  : 0ull;
        u64 w4 = ok ? *reinterpret_cast<const u64*>(bhi + 8)  : 0ull;
        u64 w5 = ok ? *reinterpret_cast<const u64*>(bhi + 10) : 0ull;
        u64 w6 = ok ? *reinterpret_cast<const u64*>(bhi + 12) : 0ull;
        u64 w7 = ok ? *reinterpret_cast<const u64*>(bhi + 14) : 0ull;
        u64 x0 = pack2(t0, t0), x1 = pack2(t1, t1);
        u64 x2 = pack2(t2, t2), x3 = pack2(t3, t3);
        fma2(accA[0], x0, w0);  fma2(accA[1], x0, w1);
        fma2(accA[2], x0, w2);  fma2(accA[3], x0, w3);
        fma2(accA[4], x0, w4);  fma2(accA[5], x0, w5);
        fma2(accA[6], x0, w6);  fma2(accA[7], x0, w7);
        fma2(accA[8],  x1, w0); fma2(accA[9],  x1, w1);
        fma2(accA[10], x1, w2); fma2(accA[11], x1, w3);
        fma2(accA[12], x1, w4); fma2(accA[13], x1, w5);
        fma2(accA[14], x1, w6); fma2(accA[15], x1, w7);
        fma2(accB[0], x2, w0);  fma2(accB[1], x2, w1);
        fma2(accB[2], x2, w2);  fma2(accB[3], x2, w3);
        fma2(accB[4], x2, w4);  fma2(accB[5], x2, w5);
        fma2(accB[6], x2, w6);  fma2(accB[7], x2, w7);
        fma2(accB[8],  x3, w0); fma2(accB[9],  x3, w1);
        fma2(accB[10], x3, w2); fma2(accB[11], x3, w3);
        fma2(accB[12], x3, w4); fma2(accB[13], x3, w5);
        fma2(accB[14], x3, w6); fma2(accB[15], x3, w7);
    }

    u64 sA = fold16(accA, lane);
    u64 sB = fold16(accB, lane);
    int lb = lane & 15;
    int vidx = ((lb & 1) << 3) | ((lb & 2) << 1) | ((lb & 4) >> 1) | ((lb & 8) >> 3);
    int r = ((lane < 16) ? 0 : 2) + (vidx >> 3);
    int p = vidx & 7;
    u64 s = (lane < 16) ? sA : sB;
    int grow = r0 + r;
    if (grow < n) {
        float dd = g_dis[grow];
        float lo, hi; unpack2(s, lo, hi);
        *reinterpret_cast<float2*>(&g_h1[(size_t)grow * 16 + 2 * p]) =
            make_float2(lo * dd, hi * dd);
    }
}

// ---------------------------------------------------------------------------
// (5) blocksum + last-block scan of block sums (fused)
// ---------------------------------------------------------------------------
__global__ void k_blocksum(int n, int nb) {
    __shared__ int swarp[8];
    __shared__ int slast;
    int t = threadIdx.x;
    int base = blockIdx.x * SCAN_BLK + t * 4;
    int s = 0;
    if (base + 3 < n) {
        int4 c = *reinterpret_cast<const int4*>(&g_cnt[base]);
        s = c.x + c.y + c.z + c.w;
    } else {
#pragma unroll
        for (int j = 0; j < 4; ++j) if (base + j < n) s += g_cnt[base + j];
    }
#pragma unroll
    for (int off = 16; off > 0; off >>= 1) s += __shfl_xor_sync(~0u, s, off);
    if ((t & 31) == 0) swarp[t >> 5] = s;
    __syncthreads();
    if (t == 0) {
        int v = 0;
#pragma unroll
        for (int j = 0; j < 8; ++j) v += swarp[j];
        g_bsum[blockIdx.x] = v;
        __threadfence();
        int ticket = atomicAdd(&g_done, 1);
        slast = (ticket == nb - 1) ? 1 : 0;
    }
    __syncthreads();
    if (!slast) return;

    __shared__ int sw2[4];
    int v = (t < nb) ? *(volatile int*)&g_bsum[t] : 0;
    int lane = t & 31, w = t >> 5;
    int incl = v;
#pragma unroll
    for (int off = 1; off < 32; off <<= 1) {
        int o = __shfl_up_sync(~0u, incl, off);
        if (lane >= off) incl += o;
    }
    if (lane == 31 && w < 4) sw2[w] = incl;
    __syncthreads();
    if (t < 128) {
        int wbase = 0;
#pragma unroll
        for (int j = 0; j < 4; ++j) wbase += (j < w) ? sw2[j] : 0;
        incl += wbase;
        if (t < nb) g_bbase[t] = incl - v;
        if (t == nb - 1) g_off[n] = incl;
    }
}

// ---------------------------------------------------------------------------
// (6) offsets
// ---------------------------------------------------------------------------
__global__ void k_offsets(int n) {
    __shared__ int swarp[8];
    int t = threadIdx.x;
    int base = blockIdx.x * SCAN_BLK + t * 4;
    int c0 = 0, c1 = 0, c2 = 0, c3 = 0;
    if (base + 3 < n) {
        int4 c = *reinterpret_cast<const int4*>(&g_cnt[base]);
        c0 = c.x; c1 = c.y; c2 = c.z; c3 = c.w;
    } else {
        if (base + 0 < n) c0 = g_cnt[base + 0];
        if (base + 1 < n) c1 = g_cnt[base + 1];
        if (base + 2 < n) c2 = g_cnt[base + 2];
        if (base + 3 < n) c3 = g_cnt[base + 3];
    }
    int tsum = c0 + c1 + c2 + c3;
    int lane = t & 31, w = t >> 5;
    int incl = tsum;
#pragma unroll
    for (int off = 1; off < 32; off <<= 1) {
        int o = __shfl_up_sync(~0u, incl, off);
        if (lane >= off) incl += o;
    }
    if (lane == 31) swarp[w] = incl;
    __syncthreads();
    int wbase = 0;
#pragma unroll
    for (int j = 0; j < 8; ++j) wbase += (j < w) ? swarp[j] : 0;
    int ex = g_bbase[blockIdx.x] + wbase + incl - tsum;
    int o0 = ex, o1 = ex + c0, o2 = o1 + c1, o3 = o2 + c2;
    if (base + 3 < n) {
        *reinterpret_cast<int4*>(&g_off[base]) = make_int4(o0, o1, o2, o3);
        *reinterpret_cast<int4*>(&g_cur[base]) = make_int4(o0, o1, o2, o3);
    } else {
        if (base + 0 < n) { g_off[base + 0] = o0; g_cur[base + 0] = o0; }
        if (base + 1 < n) { g_off[base + 1] = o1; g_cur[base + 1] = o1; }
        if (base + 2 < n) { g_off[base + 2] = o2; g_cur[base + 2] = o2; }
        if (base + 3 < n) { g_off[base + 3] = o3; g_cur[base + 3] = o3; }
    }
}

// ---------------------------------------------------------------------------
// (7) fill
// ---------------------------------------------------------------------------
__global__ void k_fill(const int* __restrict__ ei, int E) {
    int t = blockIdx.x * blockDim.x + threadIdx.x;
    int e = t * 2;
    if (e >= E) return;
    int is64 = g_is64;
    if (e + 1 < E) {
        int s0, s1, d0, d1;
        if (is64) {
            const long long* ei64 = reinterpret_cast<const long long*>(ei);
            longlong2 sv = *reinterpret_cast<const longlong2*>(&ei64[e]);
            longlong2 dv = *reinterpret_cast<const longlong2*>(&ei64[E + e]);
            s0 = (int)sv.x; s1 = (int)sv.y; d0 = (int)dv.x; d1 = (int)dv.y;
        } else {
            int2 sv = *reinterpret_cast<const int2*>(&ei[e]);
            int2 dv = *reinterpret_cast<const int2*>(&ei[E + e]);
            s0 = sv.x; s1 = sv.y; d0 = dv.x; d1 = dv.y;
        }
        int p0 = atomicAdd(&g_cur[d0], 1);
        int p1 = atomicAdd(&g_cur[d1], 1);
        g_src[p0] = s0;
        g_src[p1] = s1;
    } else {
        int s = edge_at(ei, e, is64);
        int d = edge_at(ei, E + e, is64);
        g_src[atomicAdd(&g_cur[d], 1)] = s;
    }
}

// ---------------------------------------------------------------------------
// (8) agg1 + layer2 fused
// ---------------------------------------------------------------------------
__global__ void k_agg1(const float* __restrict__ b1,
                       const float* __restrict__ W2, int n) {
    __shared__ float sb1[16];
    __shared__ float sW2[16 * 7];
    if (threadIdx.x < 16) sb1[threadIdx.x] = b1[threadIdx.x];
    if (threadIdx.x < 16 * 7) sW2[threadIdx.x] = W2[threadIdx.x];
    __syncthreads();

    int gw = (blockIdx.x * blockDim.x + threadIdx.x) >> 5;
    if (gw >= n) return;
    int lane = threadIdx.x & 31;
    int slot = lane >> 2, q = lane & 3;
    int beg = g_off[gw], end = g_off[gw + 1];
    const float4* H = reinterpret_cast<const float4*>(g_h1);
    float4 acc = make_float4(0.f, 0.f, 0.f, 0.f);
    int idx = beg + slot;
    while (idx + 8 < end) {
        int s0 = g_src[idx];
        int s1 = g_src[idx + 8];
        float4 h0 = H[s0 * 4 + q];
        float4 h1v = H[s1 * 4 + q];
        acc.x += h0.x + h1v.x;
        acc.y += h0.y + h1v.y;
        acc.z += h0.z + h1v.z;
        acc.w += h0.w + h1v.w;
        idx += 16;
    }
    if (idx < end) {
        float4 h = H[g_src[idx] * 4 + q];
        acc.x += h.x; acc.y += h.y; acc.z += h.z; acc.w += h.w;
    }
#pragma unroll
    for (int off = 4; off <= 16; off <<= 1) {
        acc.x += __shfl_xor_sync(0xFFFFFFFFu, acc.x, off);
        acc.y += __shfl_xor_sync(0xFFFFFFFFu, acc.y, off);
        acc.z += __shfl_xor_sync(0xFFFFFFFFu, acc.z, off);
        acc.w += __shfl_xor_sync(0xFFFFFFFFu, acc.w, off);
    }
    float dd = g_dis[gw];
    float4 h = H[gw * 4 + q];
    float v0 = fmaxf((acc.x + h.x) * dd + sb1[q * 4 + 0], 0.0f);
    float v1 = fmaxf((acc.y + h.y) * dd + sb1[q * 4 + 1], 0.0f);
    float v2 = fmaxf((acc.z + h.z) * dd + sb1[q * 4 + 2], 0.0f);
    float v3 = fmaxf((acc.w + h.w) * dd + sb1[q * 4 + 3], 0.0f);

    float o[7];
#pragma unroll
    for (int c = 0; c < 7; ++c) {
        o[c] = v0 * sW2[(q * 4 + 0) * 7 + c];
        o[c] = fmaf(v1, sW2[(q * 4 + 1) * 7 + c], o[c]);
        o[c] = fmaf(v2, sW2[(q * 4 + 2) * 7 + c], o[c]);
        o[c] = fmaf(v3, sW2[(q * 4 + 3) * 7 + c], o[c]);
    }
#pragma unroll
    for (int c = 0; c < 7; ++c) {
        o[c] += __shfl_xor_sync(0xFFFFFFFFu, o[c], 1);
        o[c] += __shfl_xor_sync(0xFFFFFFFFu, o[c], 2);
    }
    if (lane == 0) {
        reinterpret_cast<float4*>(g_h2)[gw * 2 + 0] =
            make_float4(o[0] * dd, o[1] * dd, o[2] * dd, o[3] * dd);
        reinterpret_cast<float4*>(g_h2)[gw * 2 + 1] =
            make_float4(o[4] * dd, o[5] * dd, o[6] * dd, 0.0f);
    }
}

// ---------------------------------------------------------------------------
// (9) agg2 + log_softmax fused
// ---------------------------------------------------------------------------
__global__ void k_agg2(const float* __restrict__ b2, float* __restrict__ out, int n) {
    __shared__ float sb2[8];
    if (threadIdx.x < 7) sb2[threadIdx.x] = b2[threadIdx.x];
    if (threadIdx.x == 7) sb2[7] = 0.0f;
    __syncthreads();

    int gw = (blockIdx.x * blockDim.x + threadIdx.x) >> 5;
    if (gw >= n) return;
    int lane = threadIdx.x & 31;
    int slot = lane >> 1, h = lane & 1;
    int beg = g_off[gw], end = g_off[gw + 1];
    const float4* H = reinterpret_cast<const float4*>(g_h2);
    float4 acc = make_float4(0.f, 0.f, 0.f, 0.f);
    int idx = beg + slot;
    while (idx + 16 < end) {
        int s0 = g_src[idx];
        int s1 = g_src[idx + 16];
        float4 v0 = H[s0 * 2 + h];
        float4 v1 = H[s1 * 2 + h];
        acc.x += v0.x + v1.x;
        acc.y += v0.y + v1.y;
        acc.z += v0.z + v1.z;
        acc.w += v0.w + v1.w;
        idx += 32;
    }
    if (idx < end) {
        float4 v = H[g_src[idx] * 2 + h];
        acc.x += v.x; acc.y += v.y; acc.z += v.z; acc.w += v.w;
    }
#pragma unroll
    for (int off = 2; off <= 16; off <<= 1) {
        acc.x += __shfl_xor_sync(0xFFFFFFFFu, acc.x, off);
        acc.y += __shfl_xor_sync(0xFFFFFFFFu, acc.y, off);
        acc.z += __shfl_xor_sync(0xFFFFFFFFu, acc.z, off);
        acc.w += __shfl_xor_sync(0xFFFFFFFFu, acc.w, off);
    }
    float dd = g_dis[gw];
    float4 hv = H[gw * 2 + h];
    float4 a;
    a.x = (acc.x + hv.x) * dd + sb2[h * 4 + 0];
    a.y = (acc.y + hv.y) * dd + sb2[h * 4 + 1];
    a.z = (acc.z + hv.z) * dd + sb2[h * 4 + 2];
    a.w = (acc.w + hv.w) * dd + sb2[h * 4 + 3];
    float4 b;
    b.x = __shfl_xor_sync(0xFFFFFFFFu, a.x, 1);
    b.y = __shfl_xor_sync(0xFFFFFFFFu, a.y, 1);
    b.z = __shfl_xor_sync(0xFFFFFFFFu, a.z, 1);
    b.w = __shfl_xor_sync(0xFFFFFFFFu, a.w, 1);
    if (lane == 0) {
        float v[7] = {a.x, a.y, a.z, a.w, b.x, b.y, b.z};
        float m = v[0];
#pragma unroll
        for (int c = 1; c < 7; ++c) m = fmaxf(m, v[c]);
        float sum = 0.0f;
#pragma unroll
        for (int c = 0; c < 7; ++c) sum += expf(v[c] - m);
        float lse = logf(sum) + m;
        float* po = out + (size_t)gw * 7;
#pragma unroll
        for (int c = 0; c < 7; ++c) po[c] = v[c] - lse;
    }
}

// ---------------------------------------------------------------------------
extern "C" void kernel_launch(void* const* d_in, const int* in_sizes, int n_in,
                              void* d_out, int out_size) {
    const float* x  = (const float*)d_in[0];
    const int*   ei = (const int*)d_in[1];
    const float* W1 = (const float*)d_in[2];
    const float* b1 = (const float*)d_in[3];
    const float* W2 = (const float*)d_in[4];
    const float* b2 = (const float*)d_in[5];
    float* out = (float*)d_out;

    const int E = in_sizes[1] / 2;
    const int n = in_sizes[0] / F_IN;
    const int nb = (n + SCAN_BLK - 1) / SCAN_BLK;

    cudaFuncSetAttribute(k_gemm1, cudaFuncAttributeMaxDynamicSharedMemorySize,
                         GEMM_SMEM);

    const int T = 256;
    const int Eh = (E + 1) / 2;
    k_init    <<<(n / 4 + T - 1) / T, T>>>(n, ei, in_sizes[1]);          // #1
    k_count   <<<(Eh + T - 1) / T, T>>>(ei, E);                          // #2
    k_dis     <<<(n / 4 + T - 1) / T, T>>>(n);                           // #3
    k_gemm1   <<<(n + 31) / 32, GEMM_THREADS, GEMM_SMEM>>>(x, W1, n);    // #4 (profiled)
    k_blocksum<<<nb, 256>>>(n, nb);                                      // #5
    k_offsets <<<nb, 256>>>(n);                                          // #6
    k_fill    <<<(Eh + T - 1) / T, T>>>(ei, E);                          // #7
    k_agg1    <<<(n + 7) / 8, 256>>>(b1, W2, n);                         // #8
    k_agg2    <<<(n + 7) / 8, 256>>>(b2, out, n);                        // #9
}